// round 13
// baseline (speedup 1.0000x reference)
#include <cuda_runtime.h>
#include <cuda_fp16.h>
#include <cstdint>

#define NT   2304      // tokens
#define DIM  256       // model dim
#define KNB  289       // padded neighbors per token
#define NH   8         // heads
#define HD   32        // head dim
#define GW   48        // spatial grid width
#define NZ   4         // attention split-K factor

// scratch (allocation-free rule: device globals)
__device__ uint32_t g_x2h[NT * 128];         // raw x2, fp16 k-pairs
__device__ uint32_t g_x2fh[NT * 128];        // fused+LN x2, fp16 k-pairs
__device__ uint32_t g_x1h[NT * 128];         // x1, fp16 k-pairs
__device__ uint32_t g_wh[768 * 128];         // wqkv, fp16 k-pairs
__device__ uint32_t g_woh[256 * 128];        // wout, fp16 k-pairs
__device__ uint32_t g_qf[NH * NT * 16];      // Q (scaled*log2e) fp16 pairs
__device__ uint32_t g_kf[NH * NT * 16];      // K fp16 pairs [h][n][16]
__device__ uint32_t g_vt[NH * HD * (NT/2)];  // V^T fp16 pairs along keys
__device__ float    g_op[NZ * NT * 256];     // split-K partial O (unnormalized)
__device__ float    g_l[NZ * NH * NT];       // split-K partial softmax sums
__device__ uint32_t g_oh[NT * 128];          // merged+normalized O, fp16 pairs

__device__ __forceinline__ uint32_t h2(float a, float b) {
    __half2 h = __floats2half2_rn(a, b);
    return *reinterpret_cast<uint32_t*>(&h);
}
__device__ __forceinline__ uint32_t smem_u32(const void* p) {
    uint32_t a;
    asm("{ .reg .u64 t; cvta.to.shared.u64 t, %1; cvt.u32.u64 %0, t; }"
        : "=r"(a) : "l"(p));
    return a;
}
__device__ __forceinline__ void cp16(uint32_t s, const void* g) {
    asm volatile("cp.async.cg.shared.global [%0], [%1], 16;" :: "r"(s), "l"(g));
}
#define CP_COMMIT() asm volatile("cp.async.commit_group;" ::: "memory")
#define CP_WAIT(n)  asm volatile("cp.async.wait_group %0;" :: "n"(n) : "memory")

// exp2 of two fp32 (log2-domain) -> packed fp16 pair (lo, hi)
#define EX2PAIR(dst, lo, hi) do {                                   \
    uint32_t _p;                                                    \
    asm("cvt.rn.f16x2.f32 %0, %1, %2;" : "=r"(_p) : "f"(hi), "f"(lo)); \
    asm("ex2.approx.f16x2 %0, %0;" : "+r"(_p));                     \
    (dst) = _p; } while (0)

#define ONES_H2 0x3C003C00u

// mma.sync m16n8k16 fp16 (f32 accum)
__device__ __forceinline__ void mma_f16(float c[4], const uint32_t a[4],
                                        uint32_t b0, uint32_t b1) {
    asm volatile(
        "mma.sync.aligned.m16n8k16.row.col.f32.f16.f16.f32 "
        "{%0,%1,%2,%3}, {%4,%5,%6,%7}, {%8,%9}, {%0,%1,%2,%3};"
        : "+f"(c[0]), "+f"(c[1]), "+f"(c[2]), "+f"(c[3])
        : "r"(a[0]), "r"(a[1]), "r"(a[2]), "r"(a[3]), "r"(b0), "r"(b1));
}

// ---------------------------------------------------------------------------
// Kernel 0: pack x1, wqkv, wout, x2 to fp16 pairs
// ---------------------------------------------------------------------------
__global__ void __launch_bounds__(256)
k_prep(const float* __restrict__ x1, const float* __restrict__ w,
       const float* __restrict__ wo, const float* __restrict__ x2)
{
    const int idx = blockIdx.x * 256 + threadIdx.x;
    if (idx < NT * 128) {
        const float2 v = reinterpret_cast<const float2*>(x1)[idx];
        g_x1h[idx] = h2(v.x, v.y);
    } else if (idx < NT * 128 + 768 * 128) {
        const int j = idx - NT * 128;
        const float2 v = reinterpret_cast<const float2*>(w)[j];
        g_wh[j] = h2(v.x, v.y);
    } else if (idx < NT * 128 + 768 * 128 + 256 * 128) {
        const int j = idx - NT * 128 - 768 * 128;
        const float2 v = reinterpret_cast<const float2*>(wo)[j];
        g_woh[j] = h2(v.x, v.y);
    } else if (idx < NT * 128 + 768 * 128 + 256 * 128 + NT * 128) {
        const int j = idx - NT * 128 - 768 * 128 - 256 * 128;
        const float2 v = reinterpret_cast<const float2*>(x2)[j];
        g_x2h[j] = h2(v.x, v.y);
    }
}

// ---------------------------------------------------------------------------
// Kernel 1: neighbor attention. Phase-1 scores via fp16 mma (no-max softmax
// fused into the fragment epilogue); phase-3 fp32 weighted sum (cp.async,
// double-buffered, same as R12). Block = 4x4 token tile, 256 thr, 144 blocks.
// ---------------------------------------------------------------------------
#define XPS   260          // fp32 Xp row stride (floats), phase 3
#define XHS   132          // fp16 Xp/Xt row stride (uint32), phase 1
#define SS    20
#define NCH   64

#define OFF_XB   0                       // shared buffer region:
                                         //  phase1: 2*64*132*4 = 67584 (fp16)
                                         //  phase3: 2*64*260*4 = 133120 (fp32)
#define OFF_XTH  133120                  // 16*132*4 = 8448
#define OFF_S    141568                  // 400*20*4 = 32000
#define OFF_PTOK 173568                  // 1600
#define OFF_PPR  175168                  // 400
#define OFF_PPC  175568                  // 400 (+pad to 176000)
#define OFF_BND  176000                  // 64
#define OFF_MULT 176064                  // 64
#define OFF_N0P  176128                  // 64
#define OFF_LSM  176192                  // 64
#define OFF_RED1 176256                  // 128
#define OFF_RED2 176384                  // 128
#define SMEM_NB  176512

__global__ void __launch_bounds__(256)
k_neighbor(const float* __restrict__ x2, const float* __restrict__ gamma,
           const float* __restrict__ beta)
{
    extern __shared__ char sm[];
    uint32_t* XpH = (uint32_t*)(sm + OFF_XB);     // phase 1 view
    float*    Xp  = (float*)(sm + OFF_XB);        // phase 3 view
    uint32_t* XtH = (uint32_t*)(sm + OFF_XTH);
    float* S    = (float*)(sm + OFF_S);
    int*   ptok = (int*)(sm + OFF_PTOK);
    unsigned char* ppr = (unsigned char*)(sm + OFF_PPR);
    unsigned char* ppc = (unsigned char*)(sm + OFF_PPC);
    unsigned char* bnd = (unsigned char*)(sm + OFF_BND);
    float* multf = (float*)(sm + OFF_MULT);
    int*   n0p   = (int*)(sm + OFF_N0P);
    float* lsm   = (float*)(sm + OFF_LSM);
    float* red1  = (float*)(sm + OFF_RED1);
    float* red2  = (float*)(sm + OFF_RED2);
    const uint32_t xb_s = smem_u32(sm + OFF_XB);

    const int t = threadIdx.x;
    const int warp = t >> 5, lane = t & 31;
    const int g = lane >> 2, tig = lane & 3;
    const int r0 = (blockIdx.x / 12) * 4;
    const int c0 = (blockIdx.x % 12) * 4;
    const int pr0 = max(r0 - 8, 0), pr1 = min(r0 + 11, GW - 1);
    const int pc0 = max(c0 - 8, 0), pc1 = min(c0 + 11, GW - 1);
    const int nr = pr1 - pr0 + 1, nc = pc1 - pc0 + 1;
    const int P  = nr * nc;

    // ---- phase 0: tables + Xt fp16 staging + per-token bounds ----
    for (int p = t; p < P; p += 256) {
        const int ir = p / nc, ic = p - ir * nc;
        ppr[p]  = (unsigned char)(pr0 + ir);
        ppc[p]  = (unsigned char)(pc0 + ic);
        ptok[p] = (pr0 + ir) * GW + (pc0 + ic);
    }
    for (int i = t; i < 16 * 32; i += 256) {     // uint4 granules
        const int lt = i >> 5, g4 = (i & 31) * 4;
        const int tok = (r0 + (lt >> 2)) * GW + (c0 + (lt & 3));
        *reinterpret_cast<uint4*>(&XtH[lt * XHS + g4]) =
            *reinterpret_cast<const uint4*>(&g_x2h[tok * 128 + g4]);
    }
    if (t < 16) {
        const int tr = r0 + (t >> 2), tc = c0 + (t & 3);
        const int rlo = max(tr - 8, 0), rhi = min(tr + 8, GW - 1);
        const int clo = max(tc - 8, 0), chi = min(tc + 8, GW - 1);
        bnd[t * 4 + 0] = (unsigned char)rlo;
        bnd[t * 4 + 1] = (unsigned char)rhi;
        bnd[t * 4 + 2] = (unsigned char)clo;
        bnd[t * 4 + 3] = (unsigned char)chi;
        const int vcnt = (rhi - rlo + 1) * (chi - clo + 1);
        multf[t] = (float)(1 + KNB - vcnt);
        n0p[t]   = (rlo - pr0) * nc + (clo - pc0);
        lsm[t]   = 0.f;
    }
    __syncthreads();

    // fp16 staging (phase 1): 64 rows x 512B
    #define STAGE_XPH(pb, buf) do {                                            \
        const int _cnt = min(NCH, P - (pb));                                    \
        for (int i = t; i < _cnt * 32; i += 256) {                              \
            const int _row = i >> 5, _g4 = (i & 31) * 4;                        \
            cp16(xb_s + (((buf) * NCH + _row) * XHS + _g4) * 4,                 \
                 &g_x2h[ptok[(pb) + _row] * 128 + _g4]);                        \
        }                                                                       \
        CP_COMMIT();                                                            \
    } while (0)

    // fp32 staging (phase 3): 64 rows x 1024B
    #define STAGE_XP(pb, buf) do {                                             \
        const int _cnt = min(NCH, P - (pb));                                    \
        for (int i = t; i < _cnt * 64; i += 256) {                              \
            const int _row = i >> 6, _f4 = i & 63;                              \
            cp16(xb_s + (((buf) * NCH + _row) * XPS + _f4 * 4) * 4,             \
                 x2 + ptok[(pb) + _row] * 256 + _f4 * 4);                       \
        }                                                                       \
        CP_COMMIT();                                                            \
    } while (0)

    // ---- phase 1: S weights via fp16 mma; warp (mt = w>>1, nb = w&1) ----
    const int mt  = warp >> 1;
    const int nb1 = warp & 1;
    const int tt0 = nb1 * 8 + 2 * tig, tt1 = tt0 + 1;
    const unsigned char rl0 = bnd[tt0*4+0], rh0 = bnd[tt0*4+1],
                        cl0 = bnd[tt0*4+2], ch0 = bnd[tt0*4+3];
    const unsigned char rl1 = bnd[tt1*4+0], rh1 = bnd[tt1*4+1],
                        cl1 = bnd[tt1*4+2], ch1 = bnd[tt1*4+3];
    float lac0 = 0.f, lac1 = 0.f;

    STAGE_XPH(0, 0);
    int buf = 0;
    for (int pb = 0; pb < P; pb += NCH) {
        const int cnt = min(NCH, P - pb);
        if (pb + NCH < P) { STAGE_XPH(pb + NCH, buf ^ 1); CP_WAIT(1); }
        else              { CP_WAIT(0); }
        __syncthreads();

        float s[4] = {0.f, 0.f, 0.f, 0.f};
        const uint32_t* A0 = &XpH[(buf * NCH + mt * 16 + g) * XHS];
        const uint32_t* A1 = &XpH[(buf * NCH + mt * 16 + 8 + g) * XHS];
        const uint32_t* B0 = &XtH[(nb1 * 8 + g) * XHS];
        #pragma unroll
        for (int ks = 0; ks < 16; ks++) {
            const uint32_t a[4] = { A0[ks * 8 + tig], A1[ks * 8 + tig],
                                    A0[ks * 8 + tig + 4], A1[ks * 8 + tig + 4] };
            mma_f16(s, a, B0[ks * 8 + tig], B0[ks * 8 + tig + 4]);
        }

        // epilogue: mask -> exp -> multiplicity -> store weights
        const int p0 = pb + mt * 16 + g;
        const int p1 = p0 + 8;
        if (mt * 16 + g < cnt) {
            const int pr = ppr[p0], pc = ppc[p0];
            float w0 = ((pr >= rl0) & (pr <= rh0) & (pc >= cl0) & (pc <= ch0))
                       ? __expf(s[0] * 0.0625f) : 0.f;
            if (p0 == n0p[tt0]) w0 *= multf[tt0];
            float w1 = ((pr >= rl1) & (pr <= rh1) & (pc >= cl1) & (pc <= ch1))
                       ? __expf(s[1] * 0.0625f) : 0.f;
            if (p0 == n0p[tt1]) w1 *= multf[tt1];
            S[p0 * SS + tt0] = w0;
            S[p0 * SS + tt1] = w1;
            lac0 += w0; lac1 += w1;
        }
        if (mt * 16 + 8 + g < cnt) {
            const int pr = ppr[p1], pc = ppc[p1];
            float w0 = ((pr >= rl0) & (pr <= rh0) & (pc >= cl0) & (pc <= ch0))
                       ? __expf(s[2] * 0.0625f) : 0.f;
            if (p1 == n0p[tt0]) w0 *= multf[tt0];
            float w1 = ((pr >= rl1) & (pr <= rh1) & (pc >= cl1) & (pc <= ch1))
                       ? __expf(s[3] * 0.0625f) : 0.f;
            if (p1 == n0p[tt1]) w1 *= multf[tt1];
            S[p1 * SS + tt0] = w0;
            S[p1 * SS + tt1] = w1;
            lac0 += w0; lac1 += w1;
        }
        __syncthreads();
        buf ^= 1;
    }

    // reduce l across g (lanes with same tig) then atomicAdd into lsm
    #pragma unroll
    for (int o = 4; o < 32; o <<= 1) {
        lac0 += __shfl_xor_sync(0xffffffffu, lac0, o);
        lac1 += __shfl_xor_sync(0xffffffffu, lac1, o);
    }
    if (g == 0) {
        atomicAdd(&lsm[tt0], lac0);
        atomicAdd(&lsm[tt1], lac1);
    }
    __syncthreads();

    // ---- phase 3: O[tok][dim] = sum_p w * Xp (fp32, cp.async, as R12) ----
    const int tx3 = t & 63;
    const int ty3 = t >> 6;
    float acc3[4][4] = {};
    STAGE_XP(0, 0);
    buf = 0;
    for (int pb = 0; pb < P; pb += NCH) {
        const int cnt = min(NCH, P - pb);
        if (pb + NCH < P) { STAGE_XP(pb + NCH, buf ^ 1); CP_WAIT(1); }
        else              { CP_WAIT(0); }
        __syncthreads();
        const float* Xb = Xp + buf * NCH * XPS;
        #pragma unroll 2
        for (int j = 0; j < cnt; j++) {
            const float4 w  = *reinterpret_cast<const float4*>(&S[(pb + j) * SS + 4 * ty3]);
            const float4 xv = *reinterpret_cast<const float4*>(Xb + j * XPS + 4 * tx3);
            acc3[0][0] += w.x * xv.x; acc3[0][1] += w.x * xv.y;
            acc3[0][2] += w.x * xv.z; acc3[0][3] += w.x * xv.w;
            acc3[1][0] += w.y * xv.x; acc3[1][1] += w.y * xv.y;
            acc3[1][2] += w.y * xv.z; acc3[1][3] += w.y * xv.w;
            acc3[2][0] += w.z * xv.x; acc3[2][1] += w.z * xv.y;
            acc3[2][2] += w.z * xv.z; acc3[2][3] += w.z * xv.w;
            acc3[3][0] += w.w * xv.x; acc3[3][1] += w.w * xv.y;
            acc3[3][2] += w.w * xv.z; acc3[3][3] += w.w * xv.w;
        }
        __syncthreads();
        buf ^= 1;
    }

    // ---- layernorm + fp16-pair output ----
    float p1s[4], p2s[4];
    #pragma unroll
    for (int tt = 0; tt < 4; tt++) {
        const float iv = 1.f / lsm[4 * ty3 + tt];
        float s1 = 0.f, s2 = 0.f;
        #pragma unroll
        for (int d = 0; d < 4; d++) {
            const float a = acc3[tt][d] * iv;
            acc3[tt][d] = a;
            s1 += a;
            s2 += a * a;
        }
        p1s[tt] = s1; p2s[tt] = s2;
    }
    #pragma unroll
    for (int o = 16; o; o >>= 1) {
        #pragma unroll
        for (int tt = 0; tt < 4; tt++) {
            p1s[tt] += __shfl_xor_sync(0xffffffffu, p1s[tt], o);
            p2s[tt] += __shfl_xor_sync(0xffffffffu, p2s[tt], o);
        }
    }
    if (lane == 0) {
        #pragma unroll
        for (int tt = 0; tt < 4; tt++) {
            red1[warp * 4 + tt] = p1s[tt];
            red2[warp * 4 + tt] = p2s[tt];
        }
    }
    __syncthreads();

    const float4 g4v = *reinterpret_cast<const float4*>(gamma + 4 * tx3);
    const float4 b4v = *reinterpret_cast<const float4*>(beta + 4 * tx3);
    #pragma unroll
    for (int tt = 0; tt < 4; tt++) {
        const int lt = 4 * ty3 + tt;
        const float s1 = red1[(2 * ty3) * 4 + tt] + red1[(2 * ty3 + 1) * 4 + tt];
        const float s2 = red2[(2 * ty3) * 4 + tt] + red2[(2 * ty3 + 1) * 4 + tt];
        const float mu   = s1 * (1.f / 256.f);
        const float var  = s2 * (1.f / 256.f) - mu * mu;
        const float rstd = rsqrtf(var + 1e-5f);
        const int tok = (r0 + (lt >> 2)) * GW + (c0 + (lt & 3));
        const float vx = (acc3[tt][0] - mu) * rstd * g4v.x + b4v.x;
        const float vy = (acc3[tt][1] - mu) * rstd * g4v.y + b4v.y;
        const float vz = (acc3[tt][2] - mu) * rstd * g4v.z + b4v.z;
        const float vw = (acc3[tt][3] - mu) * rstd * g4v.w + b4v.w;
        g_x2fh[tok * 128 + 2 * tx3]     = h2(vx, vy);
        g_x2fh[tok * 128 + 2 * tx3 + 1] = h2(vz, vw);
    }
}

// ---------------------------------------------------------------------------
// Kernel 2: fp16 QKV GEMM (R12 version). Q pre-scaled by (1/sqrt32)*log2e.
// ---------------------------------------------------------------------------
#define AHS 132
#define OFF_AH 0
#define OFF_WH 67584
#define SMEM_G16 101376

__global__ void __launch_bounds__(256)
k_gemm16(const float* __restrict__ bias)
{
    extern __shared__ char sm[];
    uint32_t* Ah = (uint32_t*)(sm + OFF_AH);
    uint32_t* Wh = (uint32_t*)(sm + OFF_WH);

    const int n0 = blockIdx.x * 64;
    const int m0 = blockIdx.y * 128;
    const uint32_t* A = (n0 < 256) ? g_x2fh : g_x1h;

    const int t = threadIdx.x;
    const int warp = t >> 5, lane = t & 31;
    const int g = lane >> 2, tig = lane & 3;

    for (int i = t; i < 128 * 32; i += 256) {
        const int r = i >> 5, c4 = (i & 31) * 4;
        *reinterpret_cast<uint4*>(&Ah[r * AHS + c4]) =
            *reinterpret_cast<const uint4*>(&A[(m0 + r) * 128 + c4]);
    }
    for (int i = t; i < 64 * 32; i += 256) {
        const int r = i >> 5, c4 = (i & 31) * 4;
        *reinterpret_cast<uint4*>(&Wh[r * AHS + c4]) =
            *reinterpret_cast<const uint4*>(&g_wh[(n0 + r) * 128 + c4]);
    }
    __syncthreads();

    float acc[8][4] = {};
    const uint32_t* A0 = &Ah[(warp * 16 + g) * AHS];
    const uint32_t* A1 = &Ah[(warp * 16 + 8 + g) * AHS];
    #pragma unroll
    for (int ks = 0; ks < 16; ks++) {
        const uint32_t a[4] = { A0[ks * 8 + tig], A1[ks * 8 + tig],
                                A0[ks * 8 + tig + 4], A1[ks * 8 + tig + 4] };
        #pragma unroll
        for (int nb = 0; nb < 8; nb++) {
            const uint32_t* wr = &Wh[(nb * 8 + g) * AHS];
            mma_f16(acc[nb], a, wr[ks * 8 + tig], wr[ks * 8 + tig + 4]);
        }
    }

    const int r0 = m0 + warp * 16 + g;
    const int r1 = r0 + 8;
    #pragma unroll
    for (int nb = 0; nb < 8; nb++) {
        const int col = n0 + nb * 8 + 2 * tig;
        const float b0v = bias[col], b1v = bias[col + 1];
        if (n0 < 256) {                       // Q, pre-scaled into log2 domain
            const float sc = 0.17677669529663687f * 1.4426950408889634f;
            const int hh = col >> 5, kd = (col & 31) >> 1;
            g_qf[(hh * NT + r0) * 16 + kd] =
                h2((acc[nb][0] + b0v) * sc, (acc[nb][1] + b1v) * sc);
            g_qf[(hh * NT + r1) * 16 + kd] =
                h2((acc[nb][2] + b0v) * sc, (acc[nb][3] + b1v) * sc);
        } else if (n0 < 512) {                // K
            const int hh = (col - 256) >> 5, kd = (col & 31) >> 1;
            g_kf[(hh * NT + r0) * 16 + kd] =
                h2(acc[nb][0] + b0v, acc[nb][1] + b1v);
            g_kf[(hh * NT + r1) * 16 + kd] =
                h2(acc[nb][2] + b0v, acc[nb][3] + b1v);
        } else {                              // V: pairs along tokens via shfl
            const int hh = (col - 512) >> 5, d0 = col & 31, d1 = d0 + 1;
            const float n0v = __shfl_down_sync(0xffffffffu, acc[nb][0], 4);
            const float n1v = __shfl_down_sync(0xffffffffu, acc[nb][1], 4);
            const float n2v = __shfl_down_sync(0xffffffffu, acc[nb][2], 4);
            const float n3v = __shfl_down_sync(0xffffffffu, acc[nb][3], 4);
            if ((g & 1) == 0) {
                g_vt[(hh * HD + d0) * (NT / 2) + (r0 >> 1)] =
                    h2(acc[nb][0] + b0v, n0v + b0v);
                g_vt[(hh * HD + d1) * (NT / 2) + (r0 >> 1)] =
                    h2(acc[nb][1] + b1v, n1v + b1v);
                g_vt[(hh * HD + d0) * (NT / 2) + (r1 >> 1)] =
                    h2(acc[nb][2] + b0v, n2v + b0v);
                g_vt[(hh * HD + d1) * (NT / 2) + (r1 >> 1)] =
                    h2(acc[nb][3] + b1v, n3v + b1v);
            }
        }
    }
}

// ---------------------------------------------------------------------------
// Kernel 3: fp16 mma.sync flash attention, split-K x4 (R12 version — kept).
// ---------------------------------------------------------------------------
#define KSS 20
#define VSS 36

__global__ void __launch_bounds__(128)
k_attn()
{
    __shared__ uint32_t Ks[2][64 * KSS];
    __shared__ uint32_t Vs[2][32 * VSS];

    const int h    = blockIdx.y;
    const int q0   = blockIdx.x * 64;
    const int z    = blockIdx.z;
    const int kofs = z * 576;
    const int vofs = z * 288;
    const int t    = threadIdx.x;
    const int warp = t >> 5, lane = t & 31;
    const int g    = lane >> 2, tig = lane & 3;

    const int kr = t >> 1, kc = (t & 1) * 8;
    const int vd = t >> 2, vc = (t & 3) * 8;

    uint32_t qf[2][4];
    {
        const uint32_t* Qp0 = &g_qf[(h * NT + q0 + warp * 16 + g) * 16];
        const uint32_t* Qp1 = &g_qf[(h * NT + q0 + warp * 16 + 8 + g) * 16];
        #pragma unroll
        for (int ks = 0; ks < 2; ks++) {
            qf[ks][0] = Qp0[ks * 8 + tig];
            qf[ks][1] = Qp1[ks * 8 + tig];
            qf[ks][2] = Qp0[ks * 8 + tig + 4];
            qf[ks][3] = Qp1[ks * 8 + tig + 4];
        }
    }

    *reinterpret_cast<uint4*>(&Ks[0][kr * KSS + kc]) =
        *reinterpret_cast<const uint4*>(&g_kf[(h * NT + kofs + kr) * 16 + kc]);
    *reinterpret_cast<uint4*>(&Ks[0][kr * KSS + kc + 4]) =
        *reinterpret_cast<const uint4*>(&g_kf[(h * NT + kofs + kr) * 16 + kc + 4]);
    *reinterpret_cast<uint4*>(&Vs[0][vd * VSS + vc]) =
        *reinterpret_cast<const uint4*>(&g_vt[(h * HD + vd) * (NT / 2) + vofs + vc]);
    *reinterpret_cast<uint4*>(&Vs[0][vd * VSS + vc + 4]) =
        *reinterpret_cast<const uint4*>(&g_vt[(h * HD + vd) * (NT / 2) + vofs + vc + 4]);
    __syncthreads();

    float o[4][4] = {};
    float lA[4] = {};

    for (int kt = 0; kt < 9; kt++) {
        const int cur = kt & 1;
        uint4 kp0, kp1, vp0, vp1;
        if (kt < 8) {
            const uint32_t* kg = &g_kf[(h * NT + kofs + (kt + 1) * 64 + kr) * 16 + kc];
            const uint32_t* vg = &g_vt[(h * HD + vd) * (NT / 2) + vofs + (kt + 1) * 32 + vc];
            kp0 = *reinterpret_cast<const uint4*>(kg);
            kp1 = *reinterpret_cast<const uint4*>(kg + 4);
            vp0 = *reinterpret_cast<const uint4*>(vg);
            vp1 = *reinterpret_cast<const uint4*>(vg + 4);
        }

        uint32_t pf[4][4];
        #pragma unroll
        for (int ks2 = 0; ks2 < 4; ks2++) {
            float s0[4] = {0.f, 0.f, 0.f, 0.f};
            float s1[4] = {0.f, 0.f, 0.f, 0.f};
            const uint32_t* kr0 = &Ks[cur][(ks2 * 16 + g) * KSS];
            const uint32_t* kr1 = &Ks[cur][(ks2 * 16 + 8 + g) * KSS];
            #pragma unroll
            for (int ks = 0; ks < 2; ks++) {
                mma_f16(s0, qf[ks], kr0[ks * 8 + tig], kr0[ks * 8 + tig + 4]);
                mma_f16(s1, qf[ks], kr1[ks * 8 + tig], kr1[ks * 8 + tig + 4]);
            }
            EX2PAIR(pf[ks2][0], s0[0], s0[1]);
            EX2PAIR(pf[ks2][1], s0[2], s0[3]);
            EX2PAIR(pf[ks2][2], s1[0], s1[1]);
            EX2PAIR(pf[ks2][3], s1[2], s1[3]);
        }

        #pragma unroll
        for (int nb = 0; nb < 4; nb++) {
            const uint32_t* vr = &Vs[cur][(nb * 8 + g) * VSS];
            #pragma unroll
            for (int ks = 0; ks < 4; ks++)
                mma_f16(o[nb], pf[ks], vr[ks * 8 + tig], vr[ks * 8 + tig + 4]);
        }
        #pragma unroll
        for (int ks = 0; ks < 4; ks++)
            mma_f16(lA, pf[ks], ONES_H2, ONES_H2);

        if (kt < 8) {
            const int nxt = cur ^ 1;
            *reinterpret_cast<uint4*>(&Ks[nxt][kr * KSS + kc])     = kp0;
            *reinterpret_cast<uint4*>(&Ks[nxt][kr * KSS + kc + 4]) = kp1;
            *reinterpret_cast<uint4*>(&Vs[nxt][vd * VSS + vc])     = vp0;
            *reinterpret_cast<uint4*>(&Vs[nxt][vd * VSS + vc + 4]) = vp1;
        }
        __syncthreads();
    }

    const int row0 = q0 + warp * 16 + g;
    if (tig == 0) {
        g_l[z * NH * NT + h * NT + row0]     = lA[0];
        g_l[z * NH * NT + h * NT + row0 + 8] = lA[2];
    }
    #pragma unroll
    for (int nb = 0; nb < 4; nb++) {
        const int col = h * 32 + nb * 8 + 2 * tig;
        *reinterpret_cast<float2*>(&g_op[(z * NT + row0) * 256 + col]) =
            make_float2(o[nb][0], o[nb][1]);
        *reinterpret_cast<float2*>(&g_op[(z * NT + row0 + 8) * 256 + col]) =
            make_float2(o[nb][2], o[nb][3]);
    }
}

// ---------------------------------------------------------------------------
// Kernel 3b: split-K merge + normalize -> g_oh (fp16 pairs).
// ---------------------------------------------------------------------------
__global__ void __launch_bounds__(256)
k_merge()
{
    const int i = blockIdx.x * 256 + threadIdx.x;   // row*64 + quad
    const int row = i >> 6, q = i & 63;
    float4 a = *reinterpret_cast<const float4*>(&g_op[row * 256 + q * 4]);
    #pragma unroll
    for (int zz = 1; zz < NZ; zz++) {
        const float4 b =
            *reinterpret_cast<const float4*>(&g_op[(zz * NT + row) * 256 + q * 4]);
        a.x += b.x; a.y += b.y; a.z += b.z; a.w += b.w;
    }
    const int hh = q >> 3;
    float lsum = 0.f;
    #pragma unroll
    for (int zz = 0; zz < NZ; zz++) lsum += g_l[zz * NH * NT + hh * NT + row];
    const float invl = 1.f / lsum;
    g_oh[row * 128 + 2 * q]     = h2(a.x * invl, a.y * invl);
    g_oh[row * 128 + 2 * q + 1] = h2(a.z * invl, a.w * invl);
}

// ---------------------------------------------------------------------------
// Kernel 4: fp16 output projection (reads g_oh). Grid (4, 36).
// ---------------------------------------------------------------------------
#define OFF_AO 0
#define OFF_WO 33792
#define SMEM_OUT16 67584

__global__ void __launch_bounds__(128)
k_gemm_out16(const float* __restrict__ bias, float* __restrict__ C)
{
    extern __shared__ char sm[];
    uint32_t* Ah = (uint32_t*)(sm + OFF_AO);
    uint32_t* Wh = (uint32_t*)(sm + OFF_WO);

    const int n0 = blockIdx.x * 64;
    const int m0 = blockIdx.y * 64;

    const int t = threadIdx.x;
    const int warp = t >> 5, lane = t & 31;
    const int g = lane >> 2, tig = lane & 3;

    for (int i = t; i < 64 * 32; i += 128) {
        const int r = i >> 5, c4 = (i & 31) * 4;
        *reinterpret_cast<uint4*>(&Ah[r * AHS + c4]) =
            *reinterpret_cast<const uint4*>(&g_oh[(m0 + r) * 128 + c4]);
        *reinterpret_cast<uint4*>(&Wh[r * AHS + c4]) =
            *reinterpret_cast<const uint4*>(&g_woh[(n0 + r) * 128 + c4]);
    }
    __syncthreads();

    float acc[8][4] = {};
    const uint32_t* A0 = &Ah[(warp * 16 + g) * AHS];
    const uint32_t* A1 = &Ah[(warp * 16 + 8 + g) * AHS];
    #pragma unroll
    for (int ks = 0; ks < 16; ks++) {
        const uint32_t a[4] = { A0[ks * 8 + tig], A1[ks * 8 + tig],
                                A0[ks * 8 + tig + 4], A1[ks * 8 + tig + 4] };
        #pragma unroll
        for (int nb = 0; nb < 8; nb++) {
            const uint32_t* wr = &Wh[(nb * 8 + g) * AHS];
            mma_f16(acc[nb], a, wr[ks * 8 + tig], wr[ks * 8 + tig + 4]);
        }
    }

    const int r0 = m0 + warp * 16 + g;
    const int r1 = r0 + 8;
    #pragma unroll
    for (int nb = 0; nb < 8; nb++) {
        const int col = n0 + nb * 8 + 2 * tig;
        const float b0v = bias[col], b1v = bias[col + 1];
        *reinterpret_cast<float2*>(C + r0 * 256 + col) =
            make_float2(acc[nb][0] + b0v, acc[nb][1] + b1v);
        *reinterpret_cast<float2*>(C + r1 * 256 + col) =
            make_float2(acc[nb][2] + b0v, acc[nb][3] + b1v);
    }
}

// ---------------------------------------------------------------------------
extern "C" void kernel_launch(void* const* d_in, const int* in_sizes, int n_in,
                              void* d_out, int out_size)
{
    const float* x1    = (const float*)d_in[0];
    const float* x2    = (const float*)d_in[1];
    const float* gamma = (const float*)d_in[2];
    const float* beta  = (const float*)d_in[3];
    const float* wqkv  = (const float*)d_in[4];
    const float* bqkv  = (const float*)d_in[5];
    const float* wout  = (const float*)d_in[6];
    const float* bout  = (const float*)d_in[7];
    float* out = (float*)d_out;

    cudaFuncSetAttribute(k_neighbor, cudaFuncAttributeMaxDynamicSharedMemorySize,
                         SMEM_NB);
    cudaFuncSetAttribute(k_gemm16, cudaFuncAttributeMaxDynamicSharedMemorySize,
                         SMEM_G16);
    cudaFuncSetAttribute(k_gemm_out16, cudaFuncAttributeMaxDynamicSharedMemorySize,
                         SMEM_OUT16);

    // 0) pack x1 + wqkv + wout + x2 to fp16
    const int prep_elems = NT * 128 + 768 * 128 + 256 * 128 + NT * 128;
    k_prep<<<(prep_elems + 255) / 256, 256>>>(x1, wqkv, wout, x2);

    // 1) neighbor attention (fp16 mma scores) + layernorm -> g_x2fh
    k_neighbor<<<144, 256, SMEM_NB>>>(x2, gamma, beta);

    // 2) QKV projections (fp16 mma) -> g_qf (log2-domain) / g_kf / g_vt
    k_gemm16<<<dim3(12, 18), 256, SMEM_G16>>>(bqkv);

    // 3) multi-head attention (fp16 mma, split-K x4, ex2.f16x2) -> g_op / g_l
    k_attn<<<dim3(36, 8, NZ), 128>>>();

    // 3b) split-K merge + normalize -> g_oh
    k_merge<<<(NT * 64) / 256, 256>>>();

    // 4) output projection (fp16 mma) -> d_out
    k_gemm_out16<<<dim3(4, 36), 128, SMEM_OUT16>>>(bout, out);
}

// round 14
// speedup vs baseline: 1.1479x; 1.1479x over previous
#include <cuda_runtime.h>
#include <cuda_fp16.h>
#include <cstdint>

#define NT   2304      // tokens
#define DIM  256       // model dim
#define KNB  289       // padded neighbors per token
#define NH   8         // heads
#define HD   32        // head dim
#define GW   48        // spatial grid width
#define NZ   4         // attention split-K factor

// scratch (allocation-free rule: device globals)
__device__ uint32_t g_x2fh[NT * 128];        // fused+LN x2, fp16 k-pairs
__device__ uint32_t g_x1h[NT * 128];         // x1, fp16 k-pairs
__device__ uint32_t g_wh[768 * 128];         // wqkv, fp16 k-pairs
__device__ uint32_t g_woh[256 * 128];        // wout, fp16 k-pairs
__device__ uint32_t g_qf[NH * NT * 16];      // Q (scaled*log2e) fp16 pairs
__device__ uint32_t g_kf[NH * NT * 16];      // K fp16 pairs [h][n][16]
__device__ uint32_t g_vt[NH * HD * (NT/2)];  // V^T fp16 pairs along keys
__device__ float    g_op[NZ * NT * 256];     // split-K partial O (unnormalized)
__device__ float    g_l[NZ * NH * NT];       // split-K partial softmax sums
__device__ uint32_t g_oh[NT * 128];          // merged+normalized O, fp16 pairs

__device__ __forceinline__ uint32_t h2(float a, float b) {
    __half2 h = __floats2half2_rn(a, b);
    return *reinterpret_cast<uint32_t*>(&h);
}
__device__ __forceinline__ uint32_t smem_u32(const void* p) {
    uint32_t a;
    asm("{ .reg .u64 t; cvta.to.shared.u64 t, %1; cvt.u32.u64 %0, t; }"
        : "=r"(a) : "l"(p));
    return a;
}
__device__ __forceinline__ void cp16(uint32_t s, const void* g) {
    asm volatile("cp.async.cg.shared.global [%0], [%1], 16;" :: "r"(s), "l"(g));
}
#define CP_COMMIT() asm volatile("cp.async.commit_group;" ::: "memory")
#define CP_WAIT(n)  asm volatile("cp.async.wait_group %0;" :: "n"(n) : "memory")

// exp2 of two fp32 (log2-domain) -> packed fp16 pair (lo, hi)
#define EX2PAIR(dst, lo, hi) do {                                   \
    uint32_t _p;                                                    \
    asm("cvt.rn.f16x2.f32 %0, %1, %2;" : "=r"(_p) : "f"(hi), "f"(lo)); \
    asm("ex2.approx.f16x2 %0, %0;" : "+r"(_p));                     \
    (dst) = _p; } while (0)

#define ONES_H2 0x3C003C00u

// ---------------------------------------------------------------------------
// Kernel 0: pack x1, wqkv, wout to fp16 pairs
// ---------------------------------------------------------------------------
__global__ void __launch_bounds__(256)
k_prep(const float* __restrict__ x1, const float* __restrict__ w,
       const float* __restrict__ wo)
{
    const int idx = blockIdx.x * 256 + threadIdx.x;
    if (idx < NT * 128) {
        const float2 v = reinterpret_cast<const float2*>(x1)[idx];
        g_x1h[idx] = h2(v.x, v.y);
    } else if (idx < NT * 128 + 768 * 128) {
        const int j = idx - NT * 128;
        const float2 v = reinterpret_cast<const float2*>(w)[j];
        g_wh[j] = h2(v.x, v.y);
    } else if (idx < NT * 128 + 768 * 128 + 256 * 128) {
        const int j = idx - NT * 128 - 768 * 128;
        const float2 v = reinterpret_cast<const float2*>(wo)[j];
        g_woh[j] = h2(v.x, v.y);
    }
}

// ---------------------------------------------------------------------------
// Kernel 1 (tiled): neighbor attention + no-max softmax + wsum + LN.
// R12 structure, but phase-2 deleted: mask->exp->multiplicity fused into the
// phase-1 chunk epilogue; l accumulated in registers, 128 atomics at the end.
// ---------------------------------------------------------------------------
#define XPS   260
#define SS    20
#define NCH   64

#define OFF_XP   0                       // 2*64*260*4 = 133120
#define OFF_XT   133120                  // 256*17*4  = 17408 (transposed)
#define OFF_S    150528                  // 400*20*4  = 32000
#define OFF_PTOK 182528                  // 1600
#define OFF_PPR  184128                  // 400
#define OFF_PPC  184528                  // 400 (+pad)
#define OFF_BND  184960                  // 64
#define OFF_MULT 185024                  // 64
#define OFF_N0P  185088                  // 64
#define OFF_LSM  185152                  // 64
#define OFF_RED1 185216                  // 128
#define OFF_RED2 185344                  // 128
#define SMEM_NB  185472

__global__ void __launch_bounds__(256)
k_neighbor(const float* __restrict__ x2, const float* __restrict__ gamma,
           const float* __restrict__ beta)
{
    extern __shared__ char sm[];
    float* Xp   = (float*)(sm + OFF_XP);
    float* XtT  = (float*)(sm + OFF_XT);
    float* S    = (float*)(sm + OFF_S);
    int*   ptok = (int*)(sm + OFF_PTOK);
    unsigned char* ppr = (unsigned char*)(sm + OFF_PPR);
    unsigned char* ppc = (unsigned char*)(sm + OFF_PPC);
    unsigned char* bnd = (unsigned char*)(sm + OFF_BND);
    float* multf = (float*)(sm + OFF_MULT);
    int*   n0p   = (int*)(sm + OFF_N0P);
    float* lsm   = (float*)(sm + OFF_LSM);
    float* red1  = (float*)(sm + OFF_RED1);
    float* red2  = (float*)(sm + OFF_RED2);
    const uint32_t xp_s = smem_u32(sm + OFF_XP);

    const int t = threadIdx.x;
    const int r0 = (blockIdx.x / 12) * 4;
    const int c0 = (blockIdx.x % 12) * 4;
    const int pr0 = max(r0 - 8, 0), pr1 = min(r0 + 11, GW - 1);
    const int pc0 = max(c0 - 8, 0), pc1 = min(c0 + 11, GW - 1);
    const int nr = pr1 - pr0 + 1, nc = pc1 - pc0 + 1;
    const int P  = nr * nc;

    // ---- phase 0: tables + Xt transposed staging + per-token constants ----
    for (int p = t; p < P; p += 256) {
        const int ir = p / nc, ic = p - ir * nc;
        ppr[p]  = (unsigned char)(pr0 + ir);
        ppc[p]  = (unsigned char)(pc0 + ic);
        ptok[p] = (pr0 + ir) * GW + (pc0 + ic);
    }
    for (int i = t; i < 16 * 64; i += 256) {
        const int lt = i >> 6, f4 = i & 63;
        const int tok = (r0 + (lt >> 2)) * GW + (c0 + (lt & 3));
        const float4 v = *reinterpret_cast<const float4*>(x2 + tok * 256 + f4 * 4);
        XtT[(4 * f4 + 0) * 17 + lt] = v.x;
        XtT[(4 * f4 + 1) * 17 + lt] = v.y;
        XtT[(4 * f4 + 2) * 17 + lt] = v.z;
        XtT[(4 * f4 + 3) * 17 + lt] = v.w;
    }
    if (t < 16) {
        const int tr = r0 + (t >> 2), tc = c0 + (t & 3);
        const int rlo = max(tr - 8, 0), rhi = min(tr + 8, GW - 1);
        const int clo = max(tc - 8, 0), chi = min(tc + 8, GW - 1);
        bnd[t * 4 + 0] = (unsigned char)rlo;
        bnd[t * 4 + 1] = (unsigned char)rhi;
        bnd[t * 4 + 2] = (unsigned char)clo;
        bnd[t * 4 + 3] = (unsigned char)chi;
        const int vcnt = (rhi - rlo + 1) * (chi - clo + 1);
        multf[t] = (float)(1 + KNB - vcnt);
        n0p[t]   = (rlo - pr0) * nc + (clo - pc0);
        lsm[t]   = 0.f;
    }
    __syncthreads();

    #define STAGE_XP(pb, buf) do {                                             \
        const int _cnt = min(NCH, P - (pb));                                    \
        for (int i = t; i < _cnt * 64; i += 256) {                              \
            const int _row = i >> 6, _f4 = i & 63;                              \
            cp16(xp_s + (((buf) * NCH + _row) * XPS + _f4 * 4) * 4,             \
                 x2 + ptok[(pb) + _row] * 256 + _f4 * 4);                       \
        }                                                                       \
        CP_COMMIT();                                                            \
    } while (0)

    // ---- phase 1: scores -> masked exp weights (fused) ----
    const int tx1 = t >> 3;
    const int ty1 = t & 7;
    const int tt0 = 2 * ty1, tt1 = tt0 + 1;
    const unsigned char rl0 = bnd[tt0*4+0], rh0 = bnd[tt0*4+1],
                        cl0 = bnd[tt0*4+2], ch0 = bnd[tt0*4+3];
    const unsigned char rl1 = bnd[tt1*4+0], rh1 = bnd[tt1*4+1],
                        cl1 = bnd[tt1*4+2], ch1 = bnd[tt1*4+3];
    const float mf0 = multf[tt0], mf1 = multf[tt1];
    const int   np0 = n0p[tt0],   np1 = n0p[tt1];
    float lac0 = 0.f, lac1 = 0.f;

    STAGE_XP(0, 0);
    int buf = 0;
    for (int pb = 0; pb < P; pb += NCH) {
        const int cnt = min(NCH, P - pb);
        if (pb + NCH < P) { STAGE_XP(pb + NCH, buf ^ 1); CP_WAIT(1); }
        else              { CP_WAIT(0); }
        __syncthreads();

        float acc[2][2] = {};
        const float* Xb = Xp + buf * NCH * XPS;
        #pragma unroll 2
        for (int k = 0; k < 256; k += 4) {
            float b0[4], b1[4];
            #pragma unroll
            for (int kk = 0; kk < 4; kk++) {
                b0[kk] = XtT[(k + kk) * 17 + tt0];
                b1[kk] = XtT[(k + kk) * 17 + tt1];
            }
            #pragma unroll
            for (int c = 0; c < 2; c++) {
                const float4 a =
                    *reinterpret_cast<const float4*>(Xb + (tx1 + 32 * c) * XPS + k);
                acc[c][0] += a.x * b0[0] + a.y * b0[1] + a.z * b0[2] + a.w * b0[3];
                acc[c][1] += a.x * b1[0] + a.y * b1[1] + a.z * b1[2] + a.w * b1[3];
            }
        }
        #pragma unroll
        for (int c = 0; c < 2; c++) {
            const int pl = tx1 + 32 * c;
            if (pl < cnt) {
                const int p = pb + pl;
                const int pr = ppr[p], pc = ppc[p];
                float w0 = ((pr >= rl0) & (pr <= rh0) & (pc >= cl0) & (pc <= ch0))
                           ? __expf(acc[c][0] * 0.0625f) : 0.f;
                if (p == np0) w0 *= mf0;
                float w1 = ((pr >= rl1) & (pr <= rh1) & (pc >= cl1) & (pc <= ch1))
                           ? __expf(acc[c][1] * 0.0625f) : 0.f;
                if (p == np1) w1 *= mf1;
                S[p * SS + tt0] = w0;
                S[p * SS + tt1] = w1;
                lac0 += w0;
                lac1 += w1;
            }
        }
        __syncthreads();
        buf ^= 1;
    }

    // reduce l across the 4 tx1-groups within each warp (lanes differ in bits 3-4)
    #pragma unroll
    for (int o = 8; o < 32; o <<= 1) {
        lac0 += __shfl_xor_sync(0xffffffffu, lac0, o);
        lac1 += __shfl_xor_sync(0xffffffffu, lac1, o);
    }
    if ((t & 31) < 8) {
        atomicAdd(&lsm[tt0], lac0);
        atomicAdd(&lsm[tt1], lac1);
    }
    __syncthreads();

    // ---- phase 3: O[tok][dim] = sum_p w * Xp (unchanged from R12) ----
    const int tx3 = t & 63;
    const int ty3 = t >> 6;
    float acc3[4][4] = {};
    STAGE_XP(0, buf);
    for (int pb = 0; pb < P; pb += NCH) {
        const int cnt = min(NCH, P - pb);
        if (pb + NCH < P) { STAGE_XP(pb + NCH, buf ^ 1); CP_WAIT(1); }
        else              { CP_WAIT(0); }
        __syncthreads();
        const float* Xb = Xp + buf * NCH * XPS;
        #pragma unroll 2
        for (int j = 0; j < cnt; j++) {
            const float4 w  = *reinterpret_cast<const float4*>(&S[(pb + j) * SS + 4 * ty3]);
            const float4 xv = *reinterpret_cast<const float4*>(Xb + j * XPS + 4 * tx3);
            acc3[0][0] += w.x * xv.x; acc3[0][1] += w.x * xv.y;
            acc3[0][2] += w.x * xv.z; acc3[0][3] += w.x * xv.w;
            acc3[1][0] += w.y * xv.x; acc3[1][1] += w.y * xv.y;
            acc3[1][2] += w.y * xv.z; acc3[1][3] += w.y * xv.w;
            acc3[2][0] += w.z * xv.x; acc3[2][1] += w.z * xv.y;
            acc3[2][2] += w.z * xv.z; acc3[2][3] += w.z * xv.w;
            acc3[3][0] += w.w * xv.x; acc3[3][1] += w.w * xv.y;
            acc3[3][2] += w.w * xv.z; acc3[3][3] += w.w * xv.w;
        }
        __syncthreads();
        buf ^= 1;
    }

    // ---- layernorm + fp16-pair output (normalize by lsm here) ----
    const int warp = t >> 5, lane = t & 31;
    float p1[4], p2[4];
    #pragma unroll
    for (int tt = 0; tt < 4; tt++) {
        const float iv = 1.f / lsm[4 * ty3 + tt];
        float s1 = 0.f, s2 = 0.f;
        #pragma unroll
        for (int d = 0; d < 4; d++) {
            const float a = acc3[tt][d] * iv;
            acc3[tt][d] = a;
            s1 += a;
            s2 += a * a;
        }
        p1[tt] = s1; p2[tt] = s2;
    }
    #pragma unroll
    for (int o = 16; o; o >>= 1) {
        #pragma unroll
        for (int tt = 0; tt < 4; tt++) {
            p1[tt] += __shfl_xor_sync(0xffffffffu, p1[tt], o);
            p2[tt] += __shfl_xor_sync(0xffffffffu, p2[tt], o);
        }
    }
    if (lane == 0) {
        #pragma unroll
        for (int tt = 0; tt < 4; tt++) {
            red1[warp * 4 + tt] = p1[tt];
            red2[warp * 4 + tt] = p2[tt];
        }
    }
    __syncthreads();

    const float4 g4 = *reinterpret_cast<const float4*>(gamma + 4 * tx3);
    const float4 b4 = *reinterpret_cast<const float4*>(beta + 4 * tx3);
    #pragma unroll
    for (int tt = 0; tt < 4; tt++) {
        const int lt = 4 * ty3 + tt;
        const float s1 = red1[(2 * ty3) * 4 + tt] + red1[(2 * ty3 + 1) * 4 + tt];
        const float s2 = red2[(2 * ty3) * 4 + tt] + red2[(2 * ty3 + 1) * 4 + tt];
        const float mu   = s1 * (1.f / 256.f);
        const float var  = s2 * (1.f / 256.f) - mu * mu;
        const float rstd = rsqrtf(var + 1e-5f);
        const int tok = (r0 + (lt >> 2)) * GW + (c0 + (lt & 3));
        const float vx = (acc3[tt][0] - mu) * rstd * g4.x + b4.x;
        const float vy = (acc3[tt][1] - mu) * rstd * g4.y + b4.y;
        const float vz = (acc3[tt][2] - mu) * rstd * g4.z + b4.z;
        const float vw = (acc3[tt][3] - mu) * rstd * g4.w + b4.w;
        g_x2fh[tok * 128 + 2 * tx3]     = h2(vx, vy);
        g_x2fh[tok * 128 + 2 * tx3 + 1] = h2(vz, vw);
    }
}

// ---------------------------------------------------------------------------
// mma.sync m16n8k16 fp16 (f32 accum)
// ---------------------------------------------------------------------------
__device__ __forceinline__ void mma_f16(float c[4], const uint32_t a[4],
                                        uint32_t b0, uint32_t b1) {
    asm volatile(
        "mma.sync.aligned.m16n8k16.row.col.f32.f16.f16.f32 "
        "{%0,%1,%2,%3}, {%4,%5,%6,%7}, {%8,%9}, {%0,%1,%2,%3};"
        : "+f"(c[0]), "+f"(c[1]), "+f"(c[2]), "+f"(c[3])
        : "r"(a[0]), "r"(a[1]), "r"(a[2]), "r"(a[3]), "r"(b0), "r"(b1));
}

// ---------------------------------------------------------------------------
// Kernel 2: fp16 QKV GEMM (R12 version). Q pre-scaled by (1/sqrt32)*log2e.
// ---------------------------------------------------------------------------
#define AHS 132
#define OFF_AH 0
#define OFF_WH 67584
#define SMEM_G16 101376

__global__ void __launch_bounds__(256)
k_gemm16(const float* __restrict__ bias)
{
    extern __shared__ char sm[];
    uint32_t* Ah = (uint32_t*)(sm + OFF_AH);
    uint32_t* Wh = (uint32_t*)(sm + OFF_WH);

    const int n0 = blockIdx.x * 64;
    const int m0 = blockIdx.y * 128;
    const uint32_t* A = (n0 < 256) ? g_x2fh : g_x1h;

    const int t = threadIdx.x;
    const int warp = t >> 5, lane = t & 31;
    const int g = lane >> 2, tig = lane & 3;

    for (int i = t; i < 128 * 32; i += 256) {
        const int r = i >> 5, c4 = (i & 31) * 4;
        *reinterpret_cast<uint4*>(&Ah[r * AHS + c4]) =
            *reinterpret_cast<const uint4*>(&A[(m0 + r) * 128 + c4]);
    }
    for (int i = t; i < 64 * 32; i += 256) {
        const int r = i >> 5, c4 = (i & 31) * 4;
        *reinterpret_cast<uint4*>(&Wh[r * AHS + c4]) =
            *reinterpret_cast<const uint4*>(&g_wh[(n0 + r) * 128 + c4]);
    }
    __syncthreads();

    float acc[8][4] = {};
    const uint32_t* A0 = &Ah[(warp * 16 + g) * AHS];
    const uint32_t* A1 = &Ah[(warp * 16 + 8 + g) * AHS];
    #pragma unroll
    for (int ks = 0; ks < 16; ks++) {
        const uint32_t a[4] = { A0[ks * 8 + tig], A1[ks * 8 + tig],
                                A0[ks * 8 + tig + 4], A1[ks * 8 + tig + 4] };
        #pragma unroll
        for (int nb = 0; nb < 8; nb++) {
            const uint32_t* wr = &Wh[(nb * 8 + g) * AHS];
            mma_f16(acc[nb], a, wr[ks * 8 + tig], wr[ks * 8 + tig + 4]);
        }
    }

    const int r0 = m0 + warp * 16 + g;
    const int r1 = r0 + 8;
    #pragma unroll
    for (int nb = 0; nb < 8; nb++) {
        const int col = n0 + nb * 8 + 2 * tig;
        const float b0v = bias[col], b1v = bias[col + 1];
        if (n0 < 256) {                       // Q, pre-scaled into log2 domain
            const float sc = 0.17677669529663687f * 1.4426950408889634f;
            const int hh = col >> 5, kd = (col & 31) >> 1;
            g_qf[(hh * NT + r0) * 16 + kd] =
                h2((acc[nb][0] + b0v) * sc, (acc[nb][1] + b1v) * sc);
            g_qf[(hh * NT + r1) * 16 + kd] =
                h2((acc[nb][2] + b0v) * sc, (acc[nb][3] + b1v) * sc);
        } else if (n0 < 512) {                // K
            const int hh = (col - 256) >> 5, kd = (col & 31) >> 1;
            g_kf[(hh * NT + r0) * 16 + kd] =
                h2(acc[nb][0] + b0v, acc[nb][1] + b1v);
            g_kf[(hh * NT + r1) * 16 + kd] =
                h2(acc[nb][2] + b0v, acc[nb][3] + b1v);
        } else {                              // V: pairs along tokens via shfl
            const int hh = (col - 512) >> 5, d0 = col & 31, d1 = d0 + 1;
            const float n0v = __shfl_down_sync(0xffffffffu, acc[nb][0], 4);
            const float n1v = __shfl_down_sync(0xffffffffu, acc[nb][1], 4);
            const float n2v = __shfl_down_sync(0xffffffffu, acc[nb][2], 4);
            const float n3v = __shfl_down_sync(0xffffffffu, acc[nb][3], 4);
            if ((g & 1) == 0) {
                g_vt[(hh * HD + d0) * (NT / 2) + (r0 >> 1)] =
                    h2(acc[nb][0] + b0v, n0v + b0v);
                g_vt[(hh * HD + d1) * (NT / 2) + (r0 >> 1)] =
                    h2(acc[nb][1] + b1v, n1v + b1v);
                g_vt[(hh * HD + d0) * (NT / 2) + (r1 >> 1)] =
                    h2(acc[nb][2] + b0v, n2v + b0v);
                g_vt[(hh * HD + d1) * (NT / 2) + (r1 >> 1)] =
                    h2(acc[nb][3] + b1v, n3v + b1v);
            }
        }
    }
}

// ---------------------------------------------------------------------------
// Kernel 3: fp16 mma.sync flash attention, split-K x4 (R12 version — kept).
// ---------------------------------------------------------------------------
#define KSS 20
#define VSS 36

__global__ void __launch_bounds__(128)
k_attn()
{
    __shared__ uint32_t Ks[2][64 * KSS];
    __shared__ uint32_t Vs[2][32 * VSS];

    const int h    = blockIdx.y;
    const int q0   = blockIdx.x * 64;
    const int z    = blockIdx.z;
    const int kofs = z * 576;
    const int vofs = z * 288;
    const int t    = threadIdx.x;
    const int warp = t >> 5, lane = t & 31;
    const int g    = lane >> 2, tig = lane & 3;

    const int kr = t >> 1, kc = (t & 1) * 8;
    const int vd = t >> 2, vc = (t & 3) * 8;

    uint32_t qf[2][4];
    {
        const uint32_t* Qp0 = &g_qf[(h * NT + q0 + warp * 16 + g) * 16];
        const uint32_t* Qp1 = &g_qf[(h * NT + q0 + warp * 16 + 8 + g) * 16];
        #pragma unroll
        for (int ks = 0; ks < 2; ks++) {
            qf[ks][0] = Qp0[ks * 8 + tig];
            qf[ks][1] = Qp1[ks * 8 + tig];
            qf[ks][2] = Qp0[ks * 8 + tig + 4];
            qf[ks][3] = Qp1[ks * 8 + tig + 4];
        }
    }

    *reinterpret_cast<uint4*>(&Ks[0][kr * KSS + kc]) =
        *reinterpret_cast<const uint4*>(&g_kf[(h * NT + kofs + kr) * 16 + kc]);
    *reinterpret_cast<uint4*>(&Ks[0][kr * KSS + kc + 4]) =
        *reinterpret_cast<const uint4*>(&g_kf[(h * NT + kofs + kr) * 16 + kc + 4]);
    *reinterpret_cast<uint4*>(&Vs[0][vd * VSS + vc]) =
        *reinterpret_cast<const uint4*>(&g_vt[(h * HD + vd) * (NT / 2) + vofs + vc]);
    *reinterpret_cast<uint4*>(&Vs[0][vd * VSS + vc + 4]) =
        *reinterpret_cast<const uint4*>(&g_vt[(h * HD + vd) * (NT / 2) + vofs + vc + 4]);
    __syncthreads();

    float o[4][4] = {};
    float lA[4] = {};

    for (int kt = 0; kt < 9; kt++) {
        const int cur = kt & 1;
        uint4 kp0, kp1, vp0, vp1;
        if (kt < 8) {
            const uint32_t* kg = &g_kf[(h * NT + kofs + (kt + 1) * 64 + kr) * 16 + kc];
            const uint32_t* vg = &g_vt[(h * HD + vd) * (NT / 2) + vofs + (kt + 1) * 32 + vc];
            kp0 = *reinterpret_cast<const uint4*>(kg);
            kp1 = *reinterpret_cast<const uint4*>(kg + 4);
            vp0 = *reinterpret_cast<const uint4*>(vg);
            vp1 = *reinterpret_cast<const uint4*>(vg + 4);
        }

        uint32_t pf[4][4];
        #pragma unroll
        for (int ks2 = 0; ks2 < 4; ks2++) {
            float s0[4] = {0.f, 0.f, 0.f, 0.f};
            float s1[4] = {0.f, 0.f, 0.f, 0.f};
            const uint32_t* kr0 = &Ks[cur][(ks2 * 16 + g) * KSS];
            const uint32_t* kr1 = &Ks[cur][(ks2 * 16 + 8 + g) * KSS];
            #pragma unroll
            for (int ks = 0; ks < 2; ks++) {
                mma_f16(s0, qf[ks], kr0[ks * 8 + tig], kr0[ks * 8 + tig + 4]);
                mma_f16(s1, qf[ks], kr1[ks * 8 + tig], kr1[ks * 8 + tig + 4]);
            }
            EX2PAIR(pf[ks2][0], s0[0], s0[1]);
            EX2PAIR(pf[ks2][1], s0[2], s0[3]);
            EX2PAIR(pf[ks2][2], s1[0], s1[1]);
            EX2PAIR(pf[ks2][3], s1[2], s1[3]);
        }

        #pragma unroll
        for (int nb = 0; nb < 4; nb++) {
            const uint32_t* vr = &Vs[cur][(nb * 8 + g) * VSS];
            #pragma unroll
            for (int ks = 0; ks < 4; ks++)
                mma_f16(o[nb], pf[ks], vr[ks * 8 + tig], vr[ks * 8 + tig + 4]);
        }
        #pragma unroll
        for (int ks = 0; ks < 4; ks++)
            mma_f16(lA, pf[ks], ONES_H2, ONES_H2);

        if (kt < 8) {
            const int nxt = cur ^ 1;
            *reinterpret_cast<uint4*>(&Ks[nxt][kr * KSS + kc])     = kp0;
            *reinterpret_cast<uint4*>(&Ks[nxt][kr * KSS + kc + 4]) = kp1;
            *reinterpret_cast<uint4*>(&Vs[nxt][vd * VSS + vc])     = vp0;
            *reinterpret_cast<uint4*>(&Vs[nxt][vd * VSS + vc + 4]) = vp1;
        }
        __syncthreads();
    }

    const int row0 = q0 + warp * 16 + g;
    if (tig == 0) {
        g_l[z * NH * NT + h * NT + row0]     = lA[0];
        g_l[z * NH * NT + h * NT + row0 + 8] = lA[2];
    }
    #pragma unroll
    for (int nb = 0; nb < 4; nb++) {
        const int col = h * 32 + nb * 8 + 2 * tig;
        *reinterpret_cast<float2*>(&g_op[(z * NT + row0) * 256 + col]) =
            make_float2(o[nb][0], o[nb][1]);
        *reinterpret_cast<float2*>(&g_op[(z * NT + row0 + 8) * 256 + col]) =
            make_float2(o[nb][2], o[nb][3]);
    }
}

// ---------------------------------------------------------------------------
// Kernel 3b: split-K merge + normalize -> g_oh (fp16 pairs).
// ---------------------------------------------------------------------------
__global__ void __launch_bounds__(256)
k_merge()
{
    const int i = blockIdx.x * 256 + threadIdx.x;   // row*64 + quad
    const int row = i >> 6, q = i & 63;
    float4 a = *reinterpret_cast<const float4*>(&g_op[row * 256 + q * 4]);
    #pragma unroll
    for (int zz = 1; zz < NZ; zz++) {
        const float4 b =
            *reinterpret_cast<const float4*>(&g_op[(zz * NT + row) * 256 + q * 4]);
        a.x += b.x; a.y += b.y; a.z += b.z; a.w += b.w;
    }
    const int hh = q >> 3;
    float lsum = 0.f;
    #pragma unroll
    for (int zz = 0; zz < NZ; zz++) lsum += g_l[zz * NH * NT + hh * NT + row];
    const float invl = 1.f / lsum;
    g_oh[row * 128 + 2 * q]     = h2(a.x * invl, a.y * invl);
    g_oh[row * 128 + 2 * q + 1] = h2(a.z * invl, a.w * invl);
}

// ---------------------------------------------------------------------------
// Kernel 4: fp16 output projection (reads g_oh). Grid (4, 36).
// ---------------------------------------------------------------------------
#define OFF_AO 0
#define OFF_WO 33792
#define SMEM_OUT16 67584

__global__ void __launch_bounds__(128)
k_gemm_out16(const float* __restrict__ bias, float* __restrict__ C)
{
    extern __shared__ char sm[];
    uint32_t* Ah = (uint32_t*)(sm + OFF_AO);
    uint32_t* Wh = (uint32_t*)(sm + OFF_WO);

    const int n0 = blockIdx.x * 64;
    const int m0 = blockIdx.y * 64;

    const int t = threadIdx.x;
    const int warp = t >> 5, lane = t & 31;
    const int g = lane >> 2, tig = lane & 3;

    for (int i = t; i < 64 * 32; i += 128) {
        const int r = i >> 5, c4 = (i & 31) * 4;
        *reinterpret_cast<uint4*>(&Ah[r * AHS + c4]) =
            *reinterpret_cast<const uint4*>(&g_oh[(m0 + r) * 128 + c4]);
        *reinterpret_cast<uint4*>(&Wh[r * AHS + c4]) =
            *reinterpret_cast<const uint4*>(&g_woh[(n0 + r) * 128 + c4]);
    }
    __syncthreads();

    float acc[8][4] = {};
    const uint32_t* A0 = &Ah[(warp * 16 + g) * AHS];
    const uint32_t* A1 = &Ah[(warp * 16 + 8 + g) * AHS];
    #pragma unroll
    for (int ks = 0; ks < 16; ks++) {
        const uint32_t a[4] = { A0[ks * 8 + tig], A1[ks * 8 + tig],
                                A0[ks * 8 + tig + 4], A1[ks * 8 + tig + 4] };
        #pragma unroll
        for (int nb = 0; nb < 8; nb++) {
            const uint32_t* wr = &Wh[(nb * 8 + g) * AHS];
            mma_f16(acc[nb], a, wr[ks * 8 + tig], wr[ks * 8 + tig + 4]);
        }
    }

    const int r0 = m0 + warp * 16 + g;
    const int r1 = r0 + 8;
    #pragma unroll
    for (int nb = 0; nb < 8; nb++) {
        const int col = n0 + nb * 8 + 2 * tig;
        const float b0v = bias[col], b1v = bias[col + 1];
        *reinterpret_cast<float2*>(C + r0 * 256 + col) =
            make_float2(acc[nb][0] + b0v, acc[nb][1] + b1v);
        *reinterpret_cast<float2*>(C + r1 * 256 + col) =
            make_float2(acc[nb][2] + b0v, acc[nb][3] + b1v);
    }
}

// ---------------------------------------------------------------------------
extern "C" void kernel_launch(void* const* d_in, const int* in_sizes, int n_in,
                              void* d_out, int out_size)
{
    const float* x1    = (const float*)d_in[0];
    const float* x2    = (const float*)d_in[1];
    const float* gamma = (const float*)d_in[2];
    const float* beta  = (const float*)d_in[3];
    const float* wqkv  = (const float*)d_in[4];
    const float* bqkv  = (const float*)d_in[5];
    const float* wout  = (const float*)d_in[6];
    const float* bout  = (const float*)d_in[7];
    float* out = (float*)d_out;

    cudaFuncSetAttribute(k_neighbor, cudaFuncAttributeMaxDynamicSharedMemorySize,
                         SMEM_NB);
    cudaFuncSetAttribute(k_gemm16, cudaFuncAttributeMaxDynamicSharedMemorySize,
                         SMEM_G16);
    cudaFuncSetAttribute(k_gemm_out16, cudaFuncAttributeMaxDynamicSharedMemorySize,
                         SMEM_OUT16);

    // 0) pack x1 + wqkv + wout to fp16
    k_prep<<<(NT * 128 + 768 * 128 + 256 * 128 + 255) / 256, 256>>>(x1, wqkv, wout);

    // 1) tiled neighbor attention (fused no-max softmax) + layernorm -> g_x2fh
    k_neighbor<<<144, 256, SMEM_NB>>>(x2, gamma, beta);

    // 2) QKV projections (fp16 mma) -> g_qf (log2-domain) / g_kf / g_vt
    k_gemm16<<<dim3(12, 18), 256, SMEM_G16>>>(bqkv);

    // 3) multi-head attention (fp16 mma, split-K x4, ex2.f16x2) -> g_op / g_l
    k_attn<<<dim3(36, 8, NZ), 128>>>();

    // 3b) split-K merge + normalize -> g_oh
    k_merge<<<(NT * 64) / 256, 256>>>();

    // 4) output projection (fp16 mma) -> d_out
    k_gemm_out16<<<dim3(4, 36), 128, SMEM_OUT16>>>(bout, out);
}

// round 15
// speedup vs baseline: 1.1695x; 1.0188x over previous
#include <cuda_runtime.h>
#include <cuda_fp16.h>
#include <cstdint>

#define NT   2304      // tokens
#define DIM  256       // model dim
#define KNB  289       // padded neighbors per token
#define NH   8         // heads
#define HD   32        // head dim
#define GW   48        // spatial grid width
#define NZ   4         // attention split-K factor

// scratch (allocation-free rule: device globals)
__device__ uint32_t g_x2fh[NT * 128];        // fused+LN x2, fp16 k-pairs
__device__ uint32_t g_qf[NH * NT * 16];      // Q (scaled*log2e) fp16 pairs
__device__ uint32_t g_kf[NH * NT * 16];      // K fp16 pairs [h][n][16]
__device__ uint32_t g_vt[NH * HD * (NT/2)];  // V^T fp16 pairs along keys
__device__ float    g_op[NZ * NT * 256];     // split-K partial O (unnormalized)
__device__ float    g_l[NZ * NH * NT];       // split-K partial softmax sums
__device__ uint32_t g_oh[NT * 128];          // merged+normalized O, fp16 pairs

__device__ __forceinline__ uint32_t h2(float a, float b) {
    __half2 h = __floats2half2_rn(a, b);
    return *reinterpret_cast<uint32_t*>(&h);
}
__device__ __forceinline__ uint32_t smem_u32(const void* p) {
    uint32_t a;
    asm("{ .reg .u64 t; cvta.to.shared.u64 t, %1; cvt.u32.u64 %0, t; }"
        : "=r"(a) : "l"(p));
    return a;
}
__device__ __forceinline__ void cp16(uint32_t s, const void* g) {
    asm volatile("cp.async.cg.shared.global [%0], [%1], 16;" :: "r"(s), "l"(g));
}
#define CP_COMMIT() asm volatile("cp.async.commit_group;" ::: "memory")
#define CP_WAIT(n)  asm volatile("cp.async.wait_group %0;" :: "n"(n) : "memory")

// exp2 of two fp32 (log2-domain) -> packed fp16 pair (lo, hi)
#define EX2PAIR(dst, lo, hi) do {                                   \
    uint32_t _p;                                                    \
    asm("cvt.rn.f16x2.f32 %0, %1, %2;" : "=r"(_p) : "f"(hi), "f"(lo)); \
    asm("ex2.approx.f16x2 %0, %0;" : "+r"(_p));                     \
    (dst) = _p; } while (0)

#define ONES_H2 0x3C003C00u

// ---------------------------------------------------------------------------
// Kernel 1 (tiled): neighbor attention + no-max softmax + wsum + LN.
// (R14 version — known good)
// ---------------------------------------------------------------------------
#define XPS   260
#define SS    20
#define NCH   64

#define OFF_XP   0
#define OFF_XT   133120
#define OFF_S    150528
#define OFF_PTOK 182528
#define OFF_PPR  184128
#define OFF_PPC  184528
#define OFF_BND  184960
#define OFF_MULT 185024
#define OFF_N0P  185088
#define OFF_LSM  185152
#define OFF_RED1 185216
#define OFF_RED2 185344
#define SMEM_NB  185472

__global__ void __launch_bounds__(256)
k_neighbor(const float* __restrict__ x2, const float* __restrict__ gamma,
           const float* __restrict__ beta)
{
    extern __shared__ char sm[];
    float* Xp   = (float*)(sm + OFF_XP);
    float* XtT  = (float*)(sm + OFF_XT);
    float* S    = (float*)(sm + OFF_S);
    int*   ptok = (int*)(sm + OFF_PTOK);
    unsigned char* ppr = (unsigned char*)(sm + OFF_PPR);
    unsigned char* ppc = (unsigned char*)(sm + OFF_PPC);
    unsigned char* bnd = (unsigned char*)(sm + OFF_BND);
    float* multf = (float*)(sm + OFF_MULT);
    int*   n0p   = (int*)(sm + OFF_N0P);
    float* lsm   = (float*)(sm + OFF_LSM);
    float* red1  = (float*)(sm + OFF_RED1);
    float* red2  = (float*)(sm + OFF_RED2);
    const uint32_t xp_s = smem_u32(sm + OFF_XP);

    const int t = threadIdx.x;
    const int r0 = (blockIdx.x / 12) * 4;
    const int c0 = (blockIdx.x % 12) * 4;
    const int pr0 = max(r0 - 8, 0), pr1 = min(r0 + 11, GW - 1);
    const int pc0 = max(c0 - 8, 0), pc1 = min(c0 + 11, GW - 1);
    const int nr = pr1 - pr0 + 1, nc = pc1 - pc0 + 1;
    const int P  = nr * nc;

    for (int p = t; p < P; p += 256) {
        const int ir = p / nc, ic = p - ir * nc;
        ppr[p]  = (unsigned char)(pr0 + ir);
        ppc[p]  = (unsigned char)(pc0 + ic);
        ptok[p] = (pr0 + ir) * GW + (pc0 + ic);
    }
    for (int i = t; i < 16 * 64; i += 256) {
        const int lt = i >> 6, f4 = i & 63;
        const int tok = (r0 + (lt >> 2)) * GW + (c0 + (lt & 3));
        const float4 v = *reinterpret_cast<const float4*>(x2 + tok * 256 + f4 * 4);
        XtT[(4 * f4 + 0) * 17 + lt] = v.x;
        XtT[(4 * f4 + 1) * 17 + lt] = v.y;
        XtT[(4 * f4 + 2) * 17 + lt] = v.z;
        XtT[(4 * f4 + 3) * 17 + lt] = v.w;
    }
    if (t < 16) {
        const int tr = r0 + (t >> 2), tc = c0 + (t & 3);
        const int rlo = max(tr - 8, 0), rhi = min(tr + 8, GW - 1);
        const int clo = max(tc - 8, 0), chi = min(tc + 8, GW - 1);
        bnd[t * 4 + 0] = (unsigned char)rlo;
        bnd[t * 4 + 1] = (unsigned char)rhi;
        bnd[t * 4 + 2] = (unsigned char)clo;
        bnd[t * 4 + 3] = (unsigned char)chi;
        const int vcnt = (rhi - rlo + 1) * (chi - clo + 1);
        multf[t] = (float)(1 + KNB - vcnt);
        n0p[t]   = (rlo - pr0) * nc + (clo - pc0);
        lsm[t]   = 0.f;
    }
    __syncthreads();

    #define STAGE_XP(pb, buf) do {                                             \
        const int _cnt = min(NCH, P - (pb));                                    \
        for (int i = t; i < _cnt * 64; i += 256) {                              \
            const int _row = i >> 6, _f4 = i & 63;                              \
            cp16(xp_s + (((buf) * NCH + _row) * XPS + _f4 * 4) * 4,             \
                 x2 + ptok[(pb) + _row] * 256 + _f4 * 4);                       \
        }                                                                       \
        CP_COMMIT();                                                            \
    } while (0)

    // ---- phase 1: scores -> masked exp weights (fused) ----
    const int tx1 = t >> 3;
    const int ty1 = t & 7;
    const int tt0 = 2 * ty1, tt1 = tt0 + 1;
    const unsigned char rl0 = bnd[tt0*4+0], rh0 = bnd[tt0*4+1],
                        cl0 = bnd[tt0*4+2], ch0 = bnd[tt0*4+3];
    const unsigned char rl1 = bnd[tt1*4+0], rh1 = bnd[tt1*4+1],
                        cl1 = bnd[tt1*4+2], ch1 = bnd[tt1*4+3];
    const float mf0 = multf[tt0], mf1 = multf[tt1];
    const int   np0 = n0p[tt0],   np1 = n0p[tt1];
    float lac0 = 0.f, lac1 = 0.f;

    STAGE_XP(0, 0);
    int buf = 0;
    for (int pb = 0; pb < P; pb += NCH) {
        const int cnt = min(NCH, P - pb);
        if (pb + NCH < P) { STAGE_XP(pb + NCH, buf ^ 1); CP_WAIT(1); }
        else              { CP_WAIT(0); }
        __syncthreads();

        float acc[2][2] = {};
        const float* Xb = Xp + buf * NCH * XPS;
        #pragma unroll 2
        for (int k = 0; k < 256; k += 4) {
            float b0[4], b1[4];
            #pragma unroll
            for (int kk = 0; kk < 4; kk++) {
                b0[kk] = XtT[(k + kk) * 17 + tt0];
                b1[kk] = XtT[(k + kk) * 17 + tt1];
            }
            #pragma unroll
            for (int c = 0; c < 2; c++) {
                const float4 a =
                    *reinterpret_cast<const float4*>(Xb + (tx1 + 32 * c) * XPS + k);
                acc[c][0] += a.x * b0[0] + a.y * b0[1] + a.z * b0[2] + a.w * b0[3];
                acc[c][1] += a.x * b1[0] + a.y * b1[1] + a.z * b1[2] + a.w * b1[3];
            }
        }
        #pragma unroll
        for (int c = 0; c < 2; c++) {
            const int pl = tx1 + 32 * c;
            if (pl < cnt) {
                const int p = pb + pl;
                const int pr = ppr[p], pc = ppc[p];
                float w0 = ((pr >= rl0) & (pr <= rh0) & (pc >= cl0) & (pc <= ch0))
                           ? __expf(acc[c][0] * 0.0625f) : 0.f;
                if (p == np0) w0 *= mf0;
                float w1 = ((pr >= rl1) & (pr <= rh1) & (pc >= cl1) & (pc <= ch1))
                           ? __expf(acc[c][1] * 0.0625f) : 0.f;
                if (p == np1) w1 *= mf1;
                S[p * SS + tt0] = w0;
                S[p * SS + tt1] = w1;
                lac0 += w0;
                lac1 += w1;
            }
        }
        __syncthreads();
        buf ^= 1;
    }

    #pragma unroll
    for (int o = 8; o < 32; o <<= 1) {
        lac0 += __shfl_xor_sync(0xffffffffu, lac0, o);
        lac1 += __shfl_xor_sync(0xffffffffu, lac1, o);
    }
    if ((t & 31) < 8) {
        atomicAdd(&lsm[tt0], lac0);
        atomicAdd(&lsm[tt1], lac1);
    }
    __syncthreads();

    // ---- phase 3: O[tok][dim] = sum_p w * Xp ----
    const int tx3 = t & 63;
    const int ty3 = t >> 6;
    float acc3[4][4] = {};
    STAGE_XP(0, buf);
    for (int pb = 0; pb < P; pb += NCH) {
        const int cnt = min(NCH, P - pb);
        if (pb + NCH < P) { STAGE_XP(pb + NCH, buf ^ 1); CP_WAIT(1); }
        else              { CP_WAIT(0); }
        __syncthreads();
        const float* Xb = Xp + buf * NCH * XPS;
        #pragma unroll 2
        for (int j = 0; j < cnt; j++) {
            const float4 w  = *reinterpret_cast<const float4*>(&S[(pb + j) * SS + 4 * ty3]);
            const float4 xv = *reinterpret_cast<const float4*>(Xb + j * XPS + 4 * tx3);
            acc3[0][0] += w.x * xv.x; acc3[0][1] += w.x * xv.y;
            acc3[0][2] += w.x * xv.z; acc3[0][3] += w.x * xv.w;
            acc3[1][0] += w.y * xv.x; acc3[1][1] += w.y * xv.y;
            acc3[1][2] += w.y * xv.z; acc3[1][3] += w.y * xv.w;
            acc3[2][0] += w.z * xv.x; acc3[2][1] += w.z * xv.y;
            acc3[2][2] += w.z * xv.z; acc3[2][3] += w.z * xv.w;
            acc3[3][0] += w.w * xv.x; acc3[3][1] += w.w * xv.y;
            acc3[3][2] += w.w * xv.z; acc3[3][3] += w.w * xv.w;
        }
        __syncthreads();
        buf ^= 1;
    }

    // ---- layernorm + fp16-pair output ----
    const int warp = t >> 5, lane = t & 31;
    float p1[4], p2[4];
    #pragma unroll
    for (int tt = 0; tt < 4; tt++) {
        const float iv = 1.f / lsm[4 * ty3 + tt];
        float s1 = 0.f, s2 = 0.f;
        #pragma unroll
        for (int d = 0; d < 4; d++) {
            const float a = acc3[tt][d] * iv;
            acc3[tt][d] = a;
            s1 += a;
            s2 += a * a;
        }
        p1[tt] = s1; p2[tt] = s2;
    }
    #pragma unroll
    for (int o = 16; o; o >>= 1) {
        #pragma unroll
        for (int tt = 0; tt < 4; tt++) {
            p1[tt] += __shfl_xor_sync(0xffffffffu, p1[tt], o);
            p2[tt] += __shfl_xor_sync(0xffffffffu, p2[tt], o);
        }
    }
    if (lane == 0) {
        #pragma unroll
        for (int tt = 0; tt < 4; tt++) {
            red1[warp * 4 + tt] = p1[tt];
            red2[warp * 4 + tt] = p2[tt];
        }
    }
    __syncthreads();

    const float4 g4 = *reinterpret_cast<const float4*>(gamma + 4 * tx3);
    const float4 b4 = *reinterpret_cast<const float4*>(beta + 4 * tx3);
    #pragma unroll
    for (int tt = 0; tt < 4; tt++) {
        const int lt = 4 * ty3 + tt;
        const float s1 = red1[(2 * ty3) * 4 + tt] + red1[(2 * ty3 + 1) * 4 + tt];
        const float s2 = red2[(2 * ty3) * 4 + tt] + red2[(2 * ty3 + 1) * 4 + tt];
        const float mu   = s1 * (1.f / 256.f);
        const float var  = s2 * (1.f / 256.f) - mu * mu;
        const float rstd = rsqrtf(var + 1e-5f);
        const int tok = (r0 + (lt >> 2)) * GW + (c0 + (lt & 3));
        const float vx = (acc3[tt][0] - mu) * rstd * g4.x + b4.x;
        const float vy = (acc3[tt][1] - mu) * rstd * g4.y + b4.y;
        const float vz = (acc3[tt][2] - mu) * rstd * g4.z + b4.z;
        const float vw = (acc3[tt][3] - mu) * rstd * g4.w + b4.w;
        g_x2fh[tok * 128 + 2 * tx3]     = h2(vx, vy);
        g_x2fh[tok * 128 + 2 * tx3 + 1] = h2(vz, vw);
    }
}

// ---------------------------------------------------------------------------
// mma.sync m16n8k16 fp16 (f32 accum)
// ---------------------------------------------------------------------------
__device__ __forceinline__ void mma_f16(float c[4], const uint32_t a[4],
                                        uint32_t b0, uint32_t b1) {
    asm volatile(
        "mma.sync.aligned.m16n8k16.row.col.f32.f16.f16.f32 "
        "{%0,%1,%2,%3}, {%4,%5,%6,%7}, {%8,%9}, {%0,%1,%2,%3};"
        : "+f"(c[0]), "+f"(c[1]), "+f"(c[2]), "+f"(c[3])
        : "r"(a[0]), "r"(a[1]), "r"(a[2]), "r"(a[3]), "r"(b0), "r"(b1));
}

// ---------------------------------------------------------------------------
// Kernel 2: fp16 QKV GEMM with inline fp32->fp16 staging (k_prep deleted).
// A = g_x2fh (fp16, Q cols) or x1 (fp32, K/V cols); W = wqkv (fp32).
// ---------------------------------------------------------------------------
#define AHS 132
#define OFF_AH 0
#define OFF_WH 67584
#define SMEM_G16 101376

__global__ void __launch_bounds__(256)
k_gemm16(const float* __restrict__ x1, const float* __restrict__ w,
         const float* __restrict__ bias)
{
    extern __shared__ char sm[];
    uint32_t* Ah = (uint32_t*)(sm + OFF_AH);
    uint32_t* Wh = (uint32_t*)(sm + OFF_WH);

    const int n0 = blockIdx.x * 64;
    const int m0 = blockIdx.y * 128;

    const int t = threadIdx.x;
    const int warp = t >> 5, lane = t & 31;
    const int g = lane >> 2, tig = lane & 3;

    if (n0 < 256) {
        for (int i = t; i < 128 * 32; i += 256) {
            const int r = i >> 5, c4 = (i & 31) * 4;
            *reinterpret_cast<uint4*>(&Ah[r * AHS + c4]) =
                *reinterpret_cast<const uint4*>(&g_x2fh[(m0 + r) * 128 + c4]);
        }
    } else {
        for (int i = t; i < 128 * 32; i += 256) {
            const int r = i >> 5, c4 = (i & 31) * 4;     // 4 pairs = 8 floats
            const float* src = x1 + (m0 + r) * 256 + c4 * 2;
            const float4 v0 = *reinterpret_cast<const float4*>(src);
            const float4 v1 = *reinterpret_cast<const float4*>(src + 4);
            uint4 pk;
            pk.x = h2(v0.x, v0.y); pk.y = h2(v0.z, v0.w);
            pk.z = h2(v1.x, v1.y); pk.w = h2(v1.z, v1.w);
            *reinterpret_cast<uint4*>(&Ah[r * AHS + c4]) = pk;
        }
    }
    for (int i = t; i < 64 * 32; i += 256) {
        const int r = i >> 5, c4 = (i & 31) * 4;
        const float* src = w + (n0 + r) * 256 + c4 * 2;
        const float4 v0 = *reinterpret_cast<const float4*>(src);
        const float4 v1 = *reinterpret_cast<const float4*>(src + 4);
        uint4 pk;
        pk.x = h2(v0.x, v0.y); pk.y = h2(v0.z, v0.w);
        pk.z = h2(v1.x, v1.y); pk.w = h2(v1.z, v1.w);
        *reinterpret_cast<uint4*>(&Wh[r * AHS + c4]) = pk;
    }
    __syncthreads();

    float acc[8][4] = {};
    const uint32_t* A0 = &Ah[(warp * 16 + g) * AHS];
    const uint32_t* A1 = &Ah[(warp * 16 + 8 + g) * AHS];
    #pragma unroll
    for (int ks = 0; ks < 16; ks++) {
        const uint32_t a[4] = { A0[ks * 8 + tig], A1[ks * 8 + tig],
                                A0[ks * 8 + tig + 4], A1[ks * 8 + tig + 4] };
        #pragma unroll
        for (int nb = 0; nb < 8; nb++) {
            const uint32_t* wr = &Wh[(nb * 8 + g) * AHS];
            mma_f16(acc[nb], a, wr[ks * 8 + tig], wr[ks * 8 + tig + 4]);
        }
    }

    const int r0 = m0 + warp * 16 + g;
    const int r1 = r0 + 8;
    #pragma unroll
    for (int nb = 0; nb < 8; nb++) {
        const int col = n0 + nb * 8 + 2 * tig;
        const float b0v = bias[col], b1v = bias[col + 1];
        if (n0 < 256) {                       // Q, pre-scaled into log2 domain
            const float sc = 0.17677669529663687f * 1.4426950408889634f;
            const int hh = col >> 5, kd = (col & 31) >> 1;
            g_qf[(hh * NT + r0) * 16 + kd] =
                h2((acc[nb][0] + b0v) * sc, (acc[nb][1] + b1v) * sc);
            g_qf[(hh * NT + r1) * 16 + kd] =
                h2((acc[nb][2] + b0v) * sc, (acc[nb][3] + b1v) * sc);
        } else if (n0 < 512) {                // K
            const int hh = (col - 256) >> 5, kd = (col & 31) >> 1;
            g_kf[(hh * NT + r0) * 16 + kd] =
                h2(acc[nb][0] + b0v, acc[nb][1] + b1v);
            g_kf[(hh * NT + r1) * 16 + kd] =
                h2(acc[nb][2] + b0v, acc[nb][3] + b1v);
        } else {                              // V: pairs along tokens via shfl
            const int hh = (col - 512) >> 5, d0 = col & 31, d1 = d0 + 1;
            const float n0v = __shfl_down_sync(0xffffffffu, acc[nb][0], 4);
            const float n1v = __shfl_down_sync(0xffffffffu, acc[nb][1], 4);
            const float n2v = __shfl_down_sync(0xffffffffu, acc[nb][2], 4);
            const float n3v = __shfl_down_sync(0xffffffffu, acc[nb][3], 4);
            if ((g & 1) == 0) {
                g_vt[(hh * HD + d0) * (NT / 2) + (r0 >> 1)] =
                    h2(acc[nb][0] + b0v, n0v + b0v);
                g_vt[(hh * HD + d1) * (NT / 2) + (r0 >> 1)] =
                    h2(acc[nb][1] + b1v, n1v + b1v);
                g_vt[(hh * HD + d0) * (NT / 2) + (r1 >> 1)] =
                    h2(acc[nb][2] + b0v, n2v + b0v);
                g_vt[(hh * HD + d1) * (NT / 2) + (r1 >> 1)] =
                    h2(acc[nb][3] + b1v, n3v + b1v);
            }
        }
    }
}

// ---------------------------------------------------------------------------
// Kernel 3: fp16 mma.sync flash attention, split-K x4 (R12/R14 version).
// ---------------------------------------------------------------------------
#define KSS 20
#define VSS 36

__global__ void __launch_bounds__(128)
k_attn()
{
    __shared__ uint32_t Ks[2][64 * KSS];
    __shared__ uint32_t Vs[2][32 * VSS];

    const int h    = blockIdx.y;
    const int q0   = blockIdx.x * 64;
    const int z    = blockIdx.z;
    const int kofs = z * 576;
    const int vofs = z * 288;
    const int t    = threadIdx.x;
    const int warp = t >> 5, lane = t & 31;
    const int g    = lane >> 2, tig = lane & 3;

    const int kr = t >> 1, kc = (t & 1) * 8;
    const int vd = t >> 2, vc = (t & 3) * 8;

    uint32_t qf[2][4];
    {
        const uint32_t* Qp0 = &g_qf[(h * NT + q0 + warp * 16 + g) * 16];
        const uint32_t* Qp1 = &g_qf[(h * NT + q0 + warp * 16 + 8 + g) * 16];
        #pragma unroll
        for (int ks = 0; ks < 2; ks++) {
            qf[ks][0] = Qp0[ks * 8 + tig];
            qf[ks][1] = Qp1[ks * 8 + tig];
            qf[ks][2] = Qp0[ks * 8 + tig + 4];
            qf[ks][3] = Qp1[ks * 8 + tig + 4];
        }
    }

    *reinterpret_cast<uint4*>(&Ks[0][kr * KSS + kc]) =
        *reinterpret_cast<const uint4*>(&g_kf[(h * NT + kofs + kr) * 16 + kc]);
    *reinterpret_cast<uint4*>(&Ks[0][kr * KSS + kc + 4]) =
        *reinterpret_cast<const uint4*>(&g_kf[(h * NT + kofs + kr) * 16 + kc + 4]);
    *reinterpret_cast<uint4*>(&Vs[0][vd * VSS + vc]) =
        *reinterpret_cast<const uint4*>(&g_vt[(h * HD + vd) * (NT / 2) + vofs + vc]);
    *reinterpret_cast<uint4*>(&Vs[0][vd * VSS + vc + 4]) =
        *reinterpret_cast<const uint4*>(&g_vt[(h * HD + vd) * (NT / 2) + vofs + vc + 4]);
    __syncthreads();

    float o[4][4] = {};
    float lA[4] = {};

    for (int kt = 0; kt < 9; kt++) {
        const int cur = kt & 1;
        uint4 kp0, kp1, vp0, vp1;
        if (kt < 8) {
            const uint32_t* kg = &g_kf[(h * NT + kofs + (kt + 1) * 64 + kr) * 16 + kc];
            const uint32_t* vg = &g_vt[(h * HD + vd) * (NT / 2) + vofs + (kt + 1) * 32 + vc];
            kp0 = *reinterpret_cast<const uint4*>(kg);
            kp1 = *reinterpret_cast<const uint4*>(kg + 4);
            vp0 = *reinterpret_cast<const uint4*>(vg);
            vp1 = *reinterpret_cast<const uint4*>(vg + 4);
        }

        uint32_t pf[4][4];
        #pragma unroll
        for (int ks2 = 0; ks2 < 4; ks2++) {
            float s0[4] = {0.f, 0.f, 0.f, 0.f};
            float s1[4] = {0.f, 0.f, 0.f, 0.f};
            const uint32_t* kr0 = &Ks[cur][(ks2 * 16 + g) * KSS];
            const uint32_t* kr1 = &Ks[cur][(ks2 * 16 + 8 + g) * KSS];
            #pragma unroll
            for (int ks = 0; ks < 2; ks++) {
                mma_f16(s0, qf[ks], kr0[ks * 8 + tig], kr0[ks * 8 + tig + 4]);
                mma_f16(s1, qf[ks], kr1[ks * 8 + tig], kr1[ks * 8 + tig + 4]);
            }
            EX2PAIR(pf[ks2][0], s0[0], s0[1]);
            EX2PAIR(pf[ks2][1], s0[2], s0[3]);
            EX2PAIR(pf[ks2][2], s1[0], s1[1]);
            EX2PAIR(pf[ks2][3], s1[2], s1[3]);
        }

        #pragma unroll
        for (int nb = 0; nb < 4; nb++) {
            const uint32_t* vr = &Vs[cur][(nb * 8 + g) * VSS];
            #pragma unroll
            for (int ks = 0; ks < 4; ks++)
                mma_f16(o[nb], pf[ks], vr[ks * 8 + tig], vr[ks * 8 + tig + 4]);
        }
        #pragma unroll
        for (int ks = 0; ks < 4; ks++)
            mma_f16(lA, pf[ks], ONES_H2, ONES_H2);

        if (kt < 8) {
            const int nxt = cur ^ 1;
            *reinterpret_cast<uint4*>(&Ks[nxt][kr * KSS + kc])     = kp0;
            *reinterpret_cast<uint4*>(&Ks[nxt][kr * KSS + kc + 4]) = kp1;
            *reinterpret_cast<uint4*>(&Vs[nxt][vd * VSS + vc])     = vp0;
            *reinterpret_cast<uint4*>(&Vs[nxt][vd * VSS + vc + 4]) = vp1;
        }
        __syncthreads();
    }

    const int row0 = q0 + warp * 16 + g;
    if (tig == 0) {
        g_l[z * NH * NT + h * NT + row0]     = lA[0];
        g_l[z * NH * NT + h * NT + row0 + 8] = lA[2];
    }
    #pragma unroll
    for (int nb = 0; nb < 4; nb++) {
        const int col = h * 32 + nb * 8 + 2 * tig;
        *reinterpret_cast<float2*>(&g_op[(z * NT + row0) * 256 + col]) =
            make_float2(o[nb][0], o[nb][1]);
        *reinterpret_cast<float2*>(&g_op[(z * NT + row0 + 8) * 256 + col]) =
            make_float2(o[nb][2], o[nb][3]);
    }
}

// ---------------------------------------------------------------------------
// Kernel 3b: split-K merge + normalize -> g_oh (fp16 pairs).
// ---------------------------------------------------------------------------
__global__ void __launch_bounds__(256)
k_merge()
{
    const int i = blockIdx.x * 256 + threadIdx.x;   // row*64 + quad
    const int row = i >> 6, q = i & 63;
    float4 a = *reinterpret_cast<const float4*>(&g_op[row * 256 + q * 4]);
    #pragma unroll
    for (int zz = 1; zz < NZ; zz++) {
        const float4 b =
            *reinterpret_cast<const float4*>(&g_op[(zz * NT + row) * 256 + q * 4]);
        a.x += b.x; a.y += b.y; a.z += b.z; a.w += b.w;
    }
    const int hh = q >> 3;
    float lsum = 0.f;
    #pragma unroll
    for (int zz = 0; zz < NZ; zz++) lsum += g_l[zz * NH * NT + hh * NT + row];
    const float invl = 1.f / lsum;
    g_oh[row * 128 + 2 * q]     = h2(a.x * invl, a.y * invl);
    g_oh[row * 128 + 2 * q + 1] = h2(a.z * invl, a.w * invl);
}

// ---------------------------------------------------------------------------
// Kernel 4: fp16 output projection; Wout staged from fp32 with inline cvt.
// ---------------------------------------------------------------------------
#define OFF_AO 0
#define OFF_WO 33792
#define SMEM_OUT16 67584

__global__ void __launch_bounds__(128)
k_gemm_out16(const float* __restrict__ wo, const float* __restrict__ bias,
             float* __restrict__ C)
{
    extern __shared__ char sm[];
    uint32_t* Ah = (uint32_t*)(sm + OFF_AO);
    uint32_t* Wh = (uint32_t*)(sm + OFF_WO);

    const int n0 = blockIdx.x * 64;
    const int m0 = blockIdx.y * 64;

    const int t = threadIdx.x;
    const int warp = t >> 5, lane = t & 31;
    const int g = lane >> 2, tig = lane & 3;

    for (int i = t; i < 64 * 32; i += 128) {
        const int r = i >> 5, c4 = (i & 31) * 4;
        *reinterpret_cast<uint4*>(&Ah[r * AHS + c4]) =
            *reinterpret_cast<const uint4*>(&g_oh[(m0 + r) * 128 + c4]);
        const float* src = wo + (n0 + r) * 256 + c4 * 2;
        const float4 v0 = *reinterpret_cast<const float4*>(src);
        const float4 v1 = *reinterpret_cast<const float4*>(src + 4);
        uint4 pk;
        pk.x = h2(v0.x, v0.y); pk.y = h2(v0.z, v0.w);
        pk.z = h2(v1.x, v1.y); pk.w = h2(v1.z, v1.w);
        *reinterpret_cast<uint4*>(&Wh[r * AHS + c4]) = pk;
    }
    __syncthreads();

    float acc[8][4] = {};
    const uint32_t* A0 = &Ah[(warp * 16 + g) * AHS];
    const uint32_t* A1 = &Ah[(warp * 16 + 8 + g) * AHS];
    #pragma unroll
    for (int ks = 0; ks < 16; ks++) {
        const uint32_t a[4] = { A0[ks * 8 + tig], A1[ks * 8 + tig],
                                A0[ks * 8 + tig + 4], A1[ks * 8 + tig + 4] };
        #pragma unroll
        for (int nb = 0; nb < 8; nb++) {
            const uint32_t* wr = &Wh[(nb * 8 + g) * AHS];
            mma_f16(acc[nb], a, wr[ks * 8 + tig], wr[ks * 8 + tig + 4]);
        }
    }

    const int r0 = m0 + warp * 16 + g;
    const int r1 = r0 + 8;
    #pragma unroll
    for (int nb = 0; nb < 8; nb++) {
        const int col = n0 + nb * 8 + 2 * tig;
        const float b0v = bias[col], b1v = bias[col + 1];
        *reinterpret_cast<float2*>(C + r0 * 256 + col) =
            make_float2(acc[nb][0] + b0v, acc[nb][1] + b1v);
        *reinterpret_cast<float2*>(C + r1 * 256 + col) =
            make_float2(acc[nb][2] + b0v, acc[nb][3] + b1v);
    }
}

// ---------------------------------------------------------------------------
extern "C" void kernel_launch(void* const* d_in, const int* in_sizes, int n_in,
                              void* d_out, int out_size)
{
    const float* x1    = (const float*)d_in[0];
    const float* x2    = (const float*)d_in[1];
    const float* gamma = (const float*)d_in[2];
    const float* beta  = (const float*)d_in[3];
    const float* wqkv  = (const float*)d_in[4];
    const float* bqkv  = (const float*)d_in[5];
    const float* wout  = (const float*)d_in[6];
    const float* bout  = (const float*)d_in[7];
    float* out = (float*)d_out;

    cudaFuncSetAttribute(k_neighbor, cudaFuncAttributeMaxDynamicSharedMemorySize,
                         SMEM_NB);
    cudaFuncSetAttribute(k_gemm16, cudaFuncAttributeMaxDynamicSharedMemorySize,
                         SMEM_G16);
    cudaFuncSetAttribute(k_gemm_out16, cudaFuncAttributeMaxDynamicSharedMemorySize,
                         SMEM_OUT16);

    // 1) tiled neighbor attention (fused no-max softmax) + layernorm -> g_x2fh
    k_neighbor<<<144, 256, SMEM_NB>>>(x2, gamma, beta);

    // 2) QKV projections (fp16 mma, inline cvt staging) -> g_qf/g_kf/g_vt
    k_gemm16<<<dim3(12, 18), 256, SMEM_G16>>>(x1, wqkv, bqkv);

    // 3) multi-head attention (fp16 mma, split-K x4, ex2.f16x2) -> g_op / g_l
    k_attn<<<dim3(36, 8, NZ), 128>>>();

    // 3b) split-K merge + normalize -> g_oh
    k_merge<<<(NT * 64) / 256, 256>>>();

    // 4) output projection (fp16 mma, inline cvt staging) -> d_out
    k_gemm_out16<<<dim3(4, 36), 128, SMEM_OUT16>>>(wout, bout, out);
}